// round 14
// baseline (speedup 1.0000x reference)
#include <cuda_runtime.h>

// WaveletTree: 3-level gated Haar DWT/IDWT tree — SINGLE KERNEL LAUNCH.
// x: [B,C,224,224] f32 -> out: [B,C,112,112] f32.
// Gate = (max|subband| > thr) is an existence test. With all 9 gates
// confirmed, idwt(dwt) telescopes: out = 2*x[:,:,1::2,1::2] exactly, needing
// only the odd input rows (half the read traffic).
//
// R14: paired-tile layout. Each thread owns one 8x16 pair of horizontally
// adjacent tiles -> single base pointer, and the pre-spin prefetch covers all
// 16 odd-row float4s of BOTH tiles (MLP 16). After the spin the fast path is
// pure stores. Producers (blocks 0..NPROBE-1) do full work on tile0 only,
// publish the gate-confirm mask ASAP, then handle tile1 like a consumer.
// All global state is idempotent across graph replays.

constexpr int HDIM = 224;
constexpr int WDIM = 224;
constexpr int OH   = 112;
constexpr int OW   = 112;
constexpr int TX   = 28;       // tiles per row (224/8)
constexpr int TY   = 28;
constexpr int TPB  = TX * TY;  // tiles per (b,c) plane
constexpr int PPR  = TX / 2;   // pairs per row = 14
constexpr int PPP  = PPR * TY; // pairs per plane = 392
constexpr int NPROBE = 64;     // producer blocks (<= wave-1 residency)
constexpr unsigned ALL_CONF = 0x1FFu;       // 9 gates
constexpr unsigned VALID_BIT = 0x80000000u; // slot valid bit

// order: [lh1, hl1, hh1, lh2, hl2, hh2, lh3, hl3, hh3]
__device__ int g_absmax[9];            // float bits as int; atomicMax-idempotent
__device__ unsigned g_probe[NPROBE];   // VALID_BIT | conf_bits, overwritten
__device__ unsigned g_done;            // slow-path completion counter (wraps)

__device__ __forceinline__ float warp_max(float v) {
#pragma unroll
    for (int o = 16; o; o >>= 1)
        v = fmaxf(v, __shfl_xor_sync(0xffffffffu, v, o));
    return v;
}

__device__ __forceinline__ unsigned warp_or(unsigned m) {
#pragma unroll
    for (int o = 16; o; o >>= 1)
        m |= __shfl_xor_sync(0xffffffffu, m, o);
    return m;
}

// Pair id -> base pointers (tile0 at xp, tile1 at xp+8; out0 at op, out1 op+4).
__device__ __forceinline__ void pair_ptrs(int P, const float* __restrict__ x,
                                          float* __restrict__ out,
                                          const float** xp, float** op) {
    int pp = P % PPP;
    int bc = P / PPP;
    int py = pp / PPR;
    int px = pp % PPR;
    *xp = x + (size_t)bc * (HDIM * WDIM) + (size_t)(py * 8) * WDIM + px * 16;
    *op = out + (size_t)bc * (OH * OW) + (size_t)(py * 4) * OW + px * 8;
}

// Single-tile pointers (fallback reconstruction only).
__device__ __forceinline__ void tile_ptrs(int t, const float* __restrict__ x,
                                          float* __restrict__ out,
                                          const float** xp, float** op) {
    int tx = t % TX;
    int r  = t / TX;
    int ty = r % TY;
    int bc = r / TY;
    *xp = x + (size_t)bc * (HDIM * WDIM) + (size_t)(ty * 8) * WDIM + tx * 8;
    *op = out + (size_t)bc * (OH * OW) + (size_t)(ty * 4) * OW + tx * 4;
}

// Full 8x8 tile load from base pointer (rows stride WDIM, cols 0..7).
__device__ __forceinline__ void load_tile(const float* __restrict__ xp,
                                          float xv[8][8]) {
#pragma unroll
    for (int rr = 0; rr < 8; rr++) {
        float4 a = __ldcs(reinterpret_cast<const float4*>(xp + rr * WDIM));
        float4 b = __ldcs(reinterpret_cast<const float4*>(xp + rr * WDIM + 4));
        xv[rr][0] = a.x; xv[rr][1] = a.y; xv[rr][2] = a.z; xv[rr][3] = a.w;
        xv[rr][4] = b.x; xv[rr][5] = b.y; xv[rr][6] = b.z; xv[rr][7] = b.w;
    }
}

// Fast-path single tile: load odd rows, store 2*x11.
__device__ __forceinline__ void fast_tile(const float* __restrict__ xp,
                                          float* __restrict__ op) {
    float4 pa[4], pb[4];
#pragma unroll
    for (int rr = 0; rr < 4; rr++) {
        const float* rp = xp + (size_t)(2 * rr + 1) * WDIM;
        pa[rr] = __ldcs(reinterpret_cast<const float4*>(rp));
        pb[rr] = __ldcs(reinterpret_cast<const float4*>(rp + 4));
    }
#pragma unroll
    for (int rr = 0; rr < 4; rr++) {
        float4 o;
        o.x = 2.0f * pa[rr].y;
        o.y = 2.0f * pa[rr].w;
        o.z = 2.0f * pb[rr].y;
        o.w = 2.0f * pb[rr].w;
        __stcs(reinterpret_cast<float4*>(op + rr * OW), o);
    }
}

// Speculative fast-path output from a fully loaded tile: out = 2*x11.
__device__ __forceinline__ void spec_store(const float xv[8][8],
                                           float* __restrict__ op) {
#pragma unroll
    for (int rr = 0; rr < 4; rr++) {
        float4 o;
        o.x = 2.0f * xv[2*rr+1][1];
        o.y = 2.0f * xv[2*rr+1][3];
        o.z = 2.0f * xv[2*rr+1][5];
        o.w = 2.0f * xv[2*rr+1][7];
        __stcs(reinterpret_cast<float4*>(op + rr * OW), o);
    }
}

// 9 per-tile subband abs-maxes from an 8x8 tile, accumulated into mx.
__device__ __forceinline__ void tile_submax(const float xv[8][8], float mx[9]) {
    float ll1[4][4];
#pragma unroll
    for (int i = 0; i < 4; i++) {
#pragma unroll
        for (int j = 0; j < 4; j++) {
            float x00 = xv[2*i][2*j],   x01 = xv[2*i][2*j+1];
            float x10 = xv[2*i+1][2*j], x11 = xv[2*i+1][2*j+1];
            float s0 = x00 + x01, s1 = x10 + x11;
            float d0 = x01 - x00, d1 = x11 - x10;
            ll1[i][j] = (s0 + s1) * 0.5f;
            mx[0] = fmaxf(mx[0], fabsf((s1 - s0) * 0.5f));
            mx[1] = fmaxf(mx[1], fabsf((d0 + d1) * 0.5f));
            mx[2] = fmaxf(mx[2], fabsf((d1 - d0) * 0.5f));
        }
    }
    float ll2[2][2];
#pragma unroll
    for (int i = 0; i < 2; i++) {
#pragma unroll
        for (int j = 0; j < 2; j++) {
            float x00 = ll1[2*i][2*j],   x01 = ll1[2*i][2*j+1];
            float x10 = ll1[2*i+1][2*j], x11 = ll1[2*i+1][2*j+1];
            float s0 = x00 + x01, s1 = x10 + x11;
            float d0 = x01 - x00, d1 = x11 - x10;
            ll2[i][j] = (s0 + s1) * 0.5f;
            mx[3] = fmaxf(mx[3], fabsf((s1 - s0) * 0.5f));
            mx[4] = fmaxf(mx[4], fabsf((d0 + d1) * 0.5f));
            mx[5] = fmaxf(mx[5], fabsf((d1 - d0) * 0.5f));
        }
    }
    {
        float x00 = ll2[0][0], x01 = ll2[0][1];
        float x10 = ll2[1][0], x11 = ll2[1][1];
        float s0 = x00 + x01, s1 = x10 + x11;
        float d0 = x01 - x00, d1 = x11 - x10;
        mx[6] = fmaxf(mx[6], fabsf((s1 - s0) * 0.5f));
        mx[7] = fmaxf(mx[7], fabsf((d0 + d1) * 0.5f));
        mx[8] = fmaxf(mx[8], fabsf((d1 - d0) * 0.5f));
    }
}

// Block-reduce 9 maxes and atomicMax into g_absmax.
__device__ __forceinline__ void absmax_publish(float mx[9]) {
    __shared__ float sred[9][8];
    int wid = threadIdx.x >> 5;
    int lid = threadIdx.x & 31;
#pragma unroll
    for (int k = 0; k < 9; k++) {
        float v = warp_max(mx[k]);
        if (lid == 0) sred[k][wid] = v;
    }
    __syncthreads();
    if (threadIdx.x < 9) {
        float v = sred[threadIdx.x][0];
#pragma unroll
        for (int w = 1; w < 8; w++) v = fmaxf(v, sred[threadIdx.x][w]);
        atomicMax(&g_absmax[threadIdx.x], __float_as_int(v));
    }
}

// Spin until all nprobe slots valid; return combined gate mask.
__device__ __forceinline__ unsigned probe_wait(int nprobe) {
    __shared__ unsigned sconf;
    if (threadIdx.x < 32) {
        volatile unsigned* vp = (volatile unsigned*)g_probe;
        unsigned vbit = VALID_BIT;
        unsigned np = (unsigned)nprobe;
        unsigned m0, m1;
        for (;;) {
            m0 = (threadIdx.x      < np) ? vp[threadIdx.x]      : vbit;
            m1 = (threadIdx.x + 32 < np) ? vp[threadIdx.x + 32] : vbit;
            bool ok = ((m0 & vbit) != 0) && ((m1 & vbit) != 0);
            if (__all_sync(0xffffffffu, ok)) break;
            __nanosleep(64);
        }
        unsigned m = (m0 | m1) & ~vbit;
        m = warp_or(m);
        if (threadIdx.x == 0) sconf = m;
    }
    __syncthreads();
    return sconf;
}

// Exact gated reconstruction for one tile (slow-path fallback only).
__device__ void reconstruct_tile(
    const float* __restrict__ xp, float* __restrict__ op,
    float G1lh, float G1hl, float G1hh,
    float G2lh, float G2hl, float G2hh,
    float G3lh, float G3hl, float G3hh) {
    float xv[8][8];
    load_tile(xp, xv);

    float ll1[4][4];
#pragma unroll
    for (int i = 0; i < 4; i++)
#pragma unroll
        for (int j = 0; j < 4; j++) {
            float x00 = xv[2*i][2*j],   x01 = xv[2*i][2*j+1];
            float x10 = xv[2*i+1][2*j], x11 = xv[2*i+1][2*j+1];
            ll1[i][j] = ((x00 + x01) + (x10 + x11)) * 0.5f;
        }

    float ll2[2][2], lh2[2][2], hl2[2][2], hh2[2][2];
#pragma unroll
    for (int i = 0; i < 2; i++)
#pragma unroll
        for (int j = 0; j < 2; j++) {
            float x00 = ll1[2*i][2*j],   x01 = ll1[2*i][2*j+1];
            float x10 = ll1[2*i+1][2*j], x11 = ll1[2*i+1][2*j+1];
            float s0 = x00 + x01, s1 = x10 + x11;
            float d0 = x01 - x00, d1 = x11 - x10;
            ll2[i][j] = (s0 + s1) * 0.5f;
            lh2[i][j] = (s1 - s0) * 0.5f;
            hl2[i][j] = (d0 + d1) * 0.5f;
            hh2[i][j] = (d1 - d0) * 0.5f;
        }

    float ll3, lh3, hl3, hh3;
    {
        float x00 = ll2[0][0], x01 = ll2[0][1];
        float x10 = ll2[1][0], x11 = ll2[1][1];
        float s0 = x00 + x01, s1 = x10 + x11;
        float d0 = x01 - x00, d1 = x11 - x10;
        ll3 = (s0 + s1) * 0.5f;
        lh3 = (s1 - s0) * 0.5f;
        hl3 = (d0 + d1) * 0.5f;
        hh3 = (d1 - d0) * 0.5f;
    }

    float r2v[2][2];
    {
        float a = ll3, b = G3lh * lh3, c = G3hl * hl3, d = G3hh * hh3;
        r2v[0][0] = (a - b - c + d) * 0.5f;
        r2v[0][1] = (a - b + c - d) * 0.5f;
        r2v[1][0] = (a + b - c - d) * 0.5f;
        r2v[1][1] = (a + b + c + d) * 0.5f;
    }

    float r1v[4][4];
#pragma unroll
    for (int i = 0; i < 2; i++)
#pragma unroll
        for (int j = 0; j < 2; j++) {
            float a = r2v[i][j];
            float b = G2lh * lh2[i][j];
            float c = G2hl * hl2[i][j];
            float d = G2hh * hh2[i][j];
            r1v[2*i][2*j]     = (a - b - c + d) * 0.5f;
            r1v[2*i][2*j+1]   = (a - b + c - d) * 0.5f;
            r1v[2*i+1][2*j]   = (a + b - c - d) * 0.5f;
            r1v[2*i+1][2*j+1] = (a + b + c + d) * 0.5f;
        }

#pragma unroll
    for (int i = 0; i < 4; i++) {
        float row[4];
#pragma unroll
        for (int j = 0; j < 4; j++) {
            float x00 = xv[2*i][2*j],   x01 = xv[2*i][2*j+1];
            float x10 = xv[2*i+1][2*j], x11 = xv[2*i+1][2*j+1];
            float s0 = x00 + x01, s1 = x10 + x11;
            float d0 = x01 - x00, d1 = x11 - x10;
            float lh1 = (s1 - s0) * 0.5f;
            float hl1 = (d0 + d1) * 0.5f;
            float hh1 = (d1 - d0) * 0.5f;
            row[j] = r1v[i][j] + G1lh * lh1 + G1hl * hl1 + G1hh * hh1;
        }
        float4 o; o.x = row[0]; o.y = row[1]; o.z = row[2]; o.w = row[3];
        __stcs(reinterpret_cast<float4*>(op + i * OW), o);
    }
}

// Slow-path finalization: publish absmax, count completion; the LAST block
// (all absmax visible) applies the exact gated reconstruction if needed.
__device__ void slow_finalize(const float* __restrict__ x,
                              float* __restrict__ out,
                              float mx[9], int total_tiles, int nblocks) {
    absmax_publish(mx);
    __threadfence();

    __shared__ unsigned slast;
    if (threadIdx.x == 0)
        slast = atomicInc(&g_done, (unsigned)nblocks - 1u);
    __syncthreads();
    if (slast != (unsigned)nblocks - 1u) return;   // not last -> done

    bool r1lh = __int_as_float(g_absmax[0]) > 0.25f;
    bool r1hl = __int_as_float(g_absmax[1]) > 0.25f;
    bool r1hh = __int_as_float(g_absmax[2]) > 0.25f;
    bool r2lh = __int_as_float(g_absmax[3]) > 0.5f;
    bool r2hl = __int_as_float(g_absmax[4]) > 0.5f;
    bool r2hh = __int_as_float(g_absmax[5]) > 0.5f;
    bool r3lh = __int_as_float(g_absmax[6]) > 1.0f;
    bool r3hl = __int_as_float(g_absmax[7]) > 1.0f;
    bool r3hh = __int_as_float(g_absmax[8]) > 1.0f;

    if (r1lh && r1hl && r1hh && r2lh && r2hl && r2hh && r3lh && r3hl && r3hh)
        return;  // speculative writes (= 2*x11) are exact

    float G3lh = r3lh ? 1.0f : 0.0f;
    float G3hl = r3hl ? 1.0f : 0.0f;
    float G3hh = r3hh ? 1.0f : 0.0f;
    float G2lh = (r2lh && r3lh) ? 1.0f : 0.0f;
    float G2hl = (r2hl && r3hl) ? 1.0f : 0.0f;
    float G2hh = (r2hh && r3hh) ? 1.0f : 0.0f;
    float G1lh = (r1lh && r2lh && r3lh) ? 1.0f : 0.0f;
    float G1hl = (r1hl && r2hl && r3hl) ? 1.0f : 0.0f;
    float G1hh = (r1hh && r2hh && r3hh) ? 1.0f : 0.0f;

    // One block reconstructs everything (correctness-only fallback).
    for (int t = threadIdx.x; t < total_tiles; t += 256) {
        const float* xp; float* op;
        tile_ptrs(t, x, out, &xp, &op);
        reconstruct_tile(xp, op, G1lh, G1hl, G1hh,
                         G2lh, G2hl, G2hh, G3lh, G3hl, G3hh);
    }
}

// ---------------------------------------------------------------------------
// The single fused kernel. 256 pairs per block (= 512 tiles).
// ---------------------------------------------------------------------------
__global__ __launch_bounds__(256, 3) void wt_main(const float* __restrict__ x,
                                                  float* __restrict__ out,
                                                  int total_pairs,
                                                  int total_tiles, int nprobe,
                                                  int nblocks) {
    int P = blockIdx.x * 256 + threadIdx.x;
    bool v = (P < total_pairs);

    const float* xp = x;
    float* op = out;
    if (v) pair_ptrs(P, x, out, &xp, &op);

    if ((int)blockIdx.x < nprobe) {
        // ===== producer: full work on tile0 ONLY, publish ASAP =====
        float mx[9];
#pragma unroll
        for (int k = 0; k < 9; k++) mx[k] = 0.0f;

        if (v) {
            float xv[8][8];
            load_tile(xp, xv);
            spec_store(xv, op);
            tile_submax(xv, mx);
        }

        unsigned mask = 0;
        {
            const float thr[9] = {0.25f, 0.25f, 0.25f, 0.5f, 0.5f, 0.5f,
                                  1.0f, 1.0f, 1.0f};
#pragma unroll
            for (int k = 0; k < 9; k++)
                if (mx[k] > thr[k]) mask |= (1u << k);
        }

        __shared__ unsigned swor[8];
        unsigned wm = warp_or(mask);
        if ((threadIdx.x & 31) == 0) swor[threadIdx.x >> 5] = wm;
        __syncthreads();
        if (threadIdx.x == 0) {
            unsigned m = swor[0];
#pragma unroll
            for (int w = 1; w < 8; w++) m |= swor[w];
            atomicExch(&g_probe[blockIdx.x], VALID_BIT | m);
        }
        __syncthreads();   // swor lifetime before other shared arrays

        // Consumer-like handling of tile1 (base xp+8, out op+4).
        unsigned conf = probe_wait(nprobe);
        if (conf == ALL_CONF) {
            if (v) fast_tile(xp + 8, op + 4);
            return;
        }
        if (v) {
            float xv[8][8];
            load_tile(xp + 8, xv);
            spec_store(xv, op + 4);
            tile_submax(xv, mx);
        }
        slow_finalize(x, out, mx, total_tiles, nblocks);
        return;
    }

    // ===== consumer: prefetch ALL odd rows of BOTH tiles, spin, branch =====
    float4 q[4][4];   // q[rr][c]: odd row (2rr+1), float4 at col 4c (c=0..3)
    if (v) {
#pragma unroll
        for (int rr = 0; rr < 4; rr++) {
            const float* rp = xp + (size_t)(2 * rr + 1) * WDIM;
            q[rr][0] = __ldcs(reinterpret_cast<const float4*>(rp));
            q[rr][1] = __ldcs(reinterpret_cast<const float4*>(rp + 4));
            q[rr][2] = __ldcs(reinterpret_cast<const float4*>(rp + 8));
            q[rr][3] = __ldcs(reinterpret_cast<const float4*>(rp + 12));
        }
    }

    unsigned conf = probe_wait(nprobe);

    if (conf == ALL_CONF) {
        if (!v) return;
        // pure stores: both tiles' outputs from the prefetch
#pragma unroll
        for (int rr = 0; rr < 4; rr++) {
            float4 o0, o1;
            o0.x = 2.0f * q[rr][0].y;
            o0.y = 2.0f * q[rr][0].w;
            o0.z = 2.0f * q[rr][1].y;
            o0.w = 2.0f * q[rr][1].w;
            o1.x = 2.0f * q[rr][2].y;
            o1.y = 2.0f * q[rr][2].w;
            o1.z = 2.0f * q[rr][3].y;
            o1.w = 2.0f * q[rr][3].w;
            __stcs(reinterpret_cast<float4*>(op + rr * OW), o0);
            __stcs(reinterpret_cast<float4*>(op + rr * OW + 4), o1);
        }
        return;
    }

    // ---- slow path: fetch even rows, exact abs-max + speculative writes ----
    float mx[9];
#pragma unroll
    for (int k = 0; k < 9; k++) mx[k] = 0.0f;

    if (v) {
        // tile0: even rows from memory, odd rows from q[..][0..1]
        float xv[8][8];
#pragma unroll
        for (int rr = 0; rr < 4; rr++) {
            const float* rp = xp + (size_t)(2 * rr) * WDIM;
            float4 a = __ldcs(reinterpret_cast<const float4*>(rp));
            float4 b = __ldcs(reinterpret_cast<const float4*>(rp + 4));
            xv[2*rr][0] = a.x; xv[2*rr][1] = a.y; xv[2*rr][2] = a.z; xv[2*rr][3] = a.w;
            xv[2*rr][4] = b.x; xv[2*rr][5] = b.y; xv[2*rr][6] = b.z; xv[2*rr][7] = b.w;
            xv[2*rr+1][0] = q[rr][0].x; xv[2*rr+1][1] = q[rr][0].y;
            xv[2*rr+1][2] = q[rr][0].z; xv[2*rr+1][3] = q[rr][0].w;
            xv[2*rr+1][4] = q[rr][1].x; xv[2*rr+1][5] = q[rr][1].y;
            xv[2*rr+1][6] = q[rr][1].z; xv[2*rr+1][7] = q[rr][1].w;
        }
        spec_store(xv, op);
        tile_submax(xv, mx);

        // tile1: even rows from memory, odd rows from q[..][2..3]
#pragma unroll
        for (int rr = 0; rr < 4; rr++) {
            const float* rp = xp + (size_t)(2 * rr) * WDIM + 8;
            float4 a = __ldcs(reinterpret_cast<const float4*>(rp));
            float4 b = __ldcs(reinterpret_cast<const float4*>(rp + 4));
            xv[2*rr][0] = a.x; xv[2*rr][1] = a.y; xv[2*rr][2] = a.z; xv[2*rr][3] = a.w;
            xv[2*rr][4] = b.x; xv[2*rr][5] = b.y; xv[2*rr][6] = b.z; xv[2*rr][7] = b.w;
            xv[2*rr+1][0] = q[rr][2].x; xv[2*rr+1][1] = q[rr][2].y;
            xv[2*rr+1][2] = q[rr][2].z; xv[2*rr+1][3] = q[rr][2].w;
            xv[2*rr+1][4] = q[rr][3].x; xv[2*rr+1][5] = q[rr][3].y;
            xv[2*rr+1][6] = q[rr][3].z; xv[2*rr+1][7] = q[rr][3].w;
        }
        spec_store(xv, op + 4);
        tile_submax(xv, mx);
    }
    slow_finalize(x, out, mx, total_tiles, nblocks);
}

extern "C" void kernel_launch(void* const* d_in, const int* in_sizes, int n_in,
                              void* d_out, int out_size) {
    const float* x = (const float*)d_in[0];
    float* out = (float*)d_out;

    int n  = in_sizes[0];
    int bc = n / (HDIM * WDIM);          // B*C planes
    int total_tiles = bc * TPB;
    int total_pairs = total_tiles / 2;
    int blocks = (total_pairs + 255) / 256;
    int nprobe = blocks < NPROBE ? blocks : NPROBE;

    wt_main<<<blocks, 256>>>(x, out, total_pairs, total_tiles, nprobe, blocks);
}